// round 4
// baseline (speedup 1.0000x reference)
#include <cuda_runtime.h>
#include <cstdint>

// QuantizationLayer: q = rint(x*8 - 0.5) (round-half-to-even), q in [0,7],
// out bits MSB-first: out[3*i + j] = (q_i >> (2-j)) & 1, as float.
//
// Output-centric mapping: thread g owns output float4 g (output floats
// 4g..4g+3). These are global bit positions 4g..4g+3 of the bit stream
// (3 bits per input element), which fall inside input elements
// e0 = floor(4g/3) and e0+1. So: 2 scalar loads (warp-contiguous window),
// 1 perfectly coalesced STG.128. Store side is 3/4 of the 512 MiB traffic,
// and becomes 4 L1 wavefronts per warp instead of 36.

__global__ __launch_bounds__(256) void quant_bits_kernel(
    const float* __restrict__ in, float4* __restrict__ out, unsigned n_out_vec)
{
    unsigned g = blockIdx.x * blockDim.x + threadIdx.x;
    if (g >= n_out_vec) return;

    unsigned base = 4u * g;                                 // global bit position of out.x
    unsigned e0   = __umulhi(base, 0xAAAAAAABu) >> 1;       // floor(base/3), exact for u32
    unsigned r    = base - 3u * e0;                         // base mod 3, in {0,1,2}

    float a = in[e0];
    float b = in[e0 + 1];

    // round-half-to-even (matches jnp.round / tf.round)
    int qa = __float2int_rn(fmaf(a, 8.0f, -0.5f));          // in [0,7]
    int qb = __float2int_rn(fmaf(b, 8.0f, -0.5f));

    // 6-bit window, MSB-first: [a2 a1 a0 b2 b1 b0]
    unsigned bits6 = ((unsigned)qa << 3) | (unsigned)qb;

    // output float j = bit (r+j) of the window = bits6 >> (5-r-j)
    unsigned s = 5u - r;
    float4 o = make_float4((float)((bits6 >> s)        & 1u),
                           (float)((bits6 >> (s - 1u)) & 1u),
                           (float)((bits6 >> (s - 2u)) & 1u),
                           (float)((bits6 >> (s - 3u)) & 1u));
    out[g] = o;
}

// Scalar fallback for out_size not divisible by 4 (never used for this shape).
__global__ void quant_bits_tail_kernel(
    const float* __restrict__ in, float* __restrict__ out,
    unsigned start, unsigned n_out)
{
    unsigned i = start + blockIdx.x * blockDim.x + threadIdx.x;
    if (i >= n_out) return;
    unsigned elem = i / 3u, bit = i - 3u * elem;
    int q = __float2int_rn(fmaf(in[elem], 8.0f, -0.5f));
    out[i] = (float)((q >> (2u - bit)) & 1);
}

extern "C" void kernel_launch(void* const* d_in, const int* in_sizes, int n_in,
                              void* d_out, int out_size)
{
    const float* x = (const float*)d_in[0];
    float* out = (float*)d_out;
    unsigned n_out = (unsigned)out_size;        // 65536 * 1536 = 100,663,296
    unsigned n_out_vec = n_out / 4u;            // 25,165,824 float4 stores

    if (n_out_vec > 0) {
        unsigned threads = 256;
        unsigned blocks = (n_out_vec + threads - 1) / threads;
        quant_bits_kernel<<<blocks, threads>>>(x, (float4*)out, n_out_vec);
    }
    unsigned tail_start = n_out_vec * 4u;
    if (tail_start < n_out) {
        unsigned tail = n_out - tail_start;
        quant_bits_tail_kernel<<<(tail + 127) / 128, 128>>>(x, out, tail_start, n_out);
    }
}

// round 5
// speedup vs baseline: 1.1822x; 1.1822x over previous
#include <cuda_runtime.h>
#include <cstdint>

// QuantizationLayer: q = rint(x*8 - 0.5) (round-half-to-even), q in [0,7],
// out bits MSB-first: out[3*i + j] = (q_i >> (2-j)) & 1, as float.
//
// Warp-cooperative tiling:
//   - warp tile = 32 input float4 (128 elems) -> 96 output float4 (384 bits)
//   - lane loads in4[tile*32 + lane]  (aligned, perfectly coalesced LDG.128)
//   - lane packs its 4 elems' 12 bits MSB-first into `pack` (bit o of the
//     lane's stream slice stored at pack bit 11-o)
//   - output vec j (j in [0,96)) covers warp-stream bits [4j, 4j+4).
//     Since 4j mod 12 in {0,4,8}, the window never crosses a pack boundary:
//     it lives in pack p = j/3 at offset o = 4*(j%3). One shuffle fetches it.
//   - lane stores output vecs j = lane, lane+32, lane+64 (coalesced STG.128)
// 4 tiles per warp, loads front-batched for MLP=4. Streaming cache hints.

static constexpr int TILES_PER_WARP = 4;
static constexpr unsigned FULL = 0xFFFFFFFFu;

__global__ __launch_bounds__(256) void quant_bits_warp_kernel(
    const float4* __restrict__ in4, float4* __restrict__ out4, unsigned n_tiles)
{
    unsigned warp_g = blockIdx.x * (blockDim.x >> 5) + (threadIdx.x >> 5);
    unsigned lane   = threadIdx.x & 31u;
    unsigned tile0  = warp_g * TILES_PER_WARP;

    // Per-lane shuffle sources/offsets (same for every tile)
    unsigned p0 = lane / 3u,          o0 = 4u * (lane - 3u * p0);
    unsigned j1 = lane + 32u;
    unsigned p1 = j1 / 3u,            o1 = 4u * (j1 - 3u * p1);
    unsigned j2 = lane + 64u;
    unsigned p2 = j2 / 3u,            o2 = 4u * (j2 - 3u * p2);

    // Front-batched loads (MLP = TILES_PER_WARP)
    float4 v[TILES_PER_WARP];
    #pragma unroll
    for (int i = 0; i < TILES_PER_WARP; i++) {
        unsigned t = tile0 + i;
        if (t < n_tiles) v[i] = __ldcs(&in4[(size_t)t * 32u + lane]);
    }

    #pragma unroll
    for (int i = 0; i < TILES_PER_WARP; i++) {
        unsigned t = tile0 + i;
        if (t >= n_tiles) continue;   // uniform across warp: shuffles stay converged

        int q0 = __float2int_rn(fmaf(v[i].x, 8.0f, -0.5f));
        int q1 = __float2int_rn(fmaf(v[i].y, 8.0f, -0.5f));
        int q2 = __float2int_rn(fmaf(v[i].z, 8.0f, -0.5f));
        int q3 = __float2int_rn(fmaf(v[i].w, 8.0f, -0.5f));

        // 12-bit pack, stream-MSB-first: bit o of slice -> pack bit 11-o
        unsigned pack = ((unsigned)q0 << 9) | ((unsigned)q1 << 6)
                      | ((unsigned)q2 << 3) |  (unsigned)q3;

        unsigned w0 = (__shfl_sync(FULL, pack, p0) >> (8u - o0)) & 0xFu;
        unsigned w1 = (__shfl_sync(FULL, pack, p1) >> (8u - o1)) & 0xFu;
        unsigned w2 = (__shfl_sync(FULL, pack, p2) >> (8u - o2)) & 0xFu;

        size_t obase = (size_t)t * 96u;
        __stcs(&out4[obase + lane],
               make_float4((float)((w0 >> 3) & 1u), (float)((w0 >> 2) & 1u),
                           (float)((w0 >> 1) & 1u), (float)( w0       & 1u)));
        __stcs(&out4[obase + j1],
               make_float4((float)((w1 >> 3) & 1u), (float)((w1 >> 2) & 1u),
                           (float)((w1 >> 1) & 1u), (float)( w1       & 1u)));
        __stcs(&out4[obase + j2],
               make_float4((float)((w2 >> 3) & 1u), (float)((w2 >> 2) & 1u),
                           (float)((w2 >> 1) & 1u), (float)( w2       & 1u)));
    }
}

// Scalar fallback for elements beyond the last full 128-elem tile
// (never launched for this shape: 33,554,432 = 128 * 262,144).
__global__ void quant_bits_tail_kernel(
    const float* __restrict__ in, float* __restrict__ out,
    unsigned start_elem, unsigned n_elem)
{
    unsigned e = start_elem + blockIdx.x * blockDim.x + threadIdx.x;
    if (e >= n_elem) return;
    int q = __float2int_rn(fmaf(in[e], 8.0f, -0.5f));
    out[3u * e + 0] = (float)((q >> 2) & 1);
    out[3u * e + 1] = (float)((q >> 1) & 1);
    out[3u * e + 2] = (float)( q       & 1);
}

extern "C" void kernel_launch(void* const* d_in, const int* in_sizes, int n_in,
                              void* d_out, int out_size)
{
    const float* x = (const float*)d_in[0];
    float* out = (float*)d_out;
    unsigned n = (unsigned)in_sizes[0];       // 33,554,432
    unsigned n_tiles = n / 128u;              // 262,144 warp tiles

    if (n_tiles > 0) {
        unsigned warps_needed  = (n_tiles + TILES_PER_WARP - 1) / TILES_PER_WARP;
        unsigned warps_per_blk = 8;           // 256 threads
        unsigned blocks = (warps_needed + warps_per_blk - 1) / warps_per_blk;
        quant_bits_warp_kernel<<<blocks, 256>>>(
            (const float4*)x, (float4*)out, n_tiles);
    }
    unsigned done = n_tiles * 128u;
    if (done < n) {
        unsigned tail = n - done;
        quant_bits_tail_kernel<<<(tail + 127) / 128, 128>>>(x, out, done, n);
    }
}